// round 15
// baseline (speedup 1.0000x reference)
#include <cuda_runtime.h>
#include <cuda_bf16.h>
#include <math.h>

#define TT 512
#define BB 32
#define KD 1024
#define GD 4096
#define NBLK 128
#define NTHR 512

// Scratch
__device__ float g_xproj[(size_t)TT * BB * GD];
__device__ __align__(16) unsigned g_hpk[2][KD * BB];   // [k][b], hi|lo<<16 packed bf16
__device__ __align__(128) unsigned g_bflag[128];  // per-block completed-step counter
__device__ unsigned g_xflag[128];   // y-chunk -> # n-tiles finished (target 32)

#define NB_REC() asm volatile("bar.sync 1, 256;" ::: "memory")
#define NB_GEM() asm volatile("bar.sync 2, 256;" ::: "memory")

// smem word offsets (4B words)
#define WFH_OFF 0          // W frags hi: 16384 words (64 KB)
#define WFL_OFF 16384      // W frags lo: 16384 words (64 KB)
#define HST_OFF 32768      // h chunk bufs: 3 x 4608 = 13824 words (55.3 KB)
#define HP_OFF  46592      // partials: 4352 words (17.4 KB) — own region
#define GX_OFF  50944      // producer single stage: 5120 words (20 KB)
#define SMEM_WORDS 56064   // 224256 B

#define CP_WAIT_2() asm volatile("cp.async.wait_group 2;" ::: "memory")
#define CP_WAIT_1() asm volatile("cp.async.wait_group 1;" ::: "memory")
#define CP_WAIT_0() asm volatile("cp.async.wait_group 0;" ::: "memory")

// ---------------------------------------------------------------------------
__global__ void init_state_kernel(const float* __restrict__ h0) {
    int i = blockIdx.x * blockDim.x + threadIdx.x;   // 0..32767 = k*32 + b
    int k = i >> 5;
    float v = h0[k];
    __nv_bfloat16 hb = __float2bfloat16_rn(v);
    __nv_bfloat16 lb = __float2bfloat16_rn(v - __bfloat162float(hb));
    g_hpk[0][i] = (unsigned)*(unsigned short*)&hb |
                  ((unsigned)*(unsigned short*)&lb << 16);
    if (i < 128) { g_bflag[i] = 0u; g_xflag[i] = 0u; }
}

// ---------------------------------------------------------------------------
__device__ __forceinline__ void mma16816(float* c,
                                         unsigned a0, unsigned a1, unsigned a2, unsigned a3,
                                         unsigned b0, unsigned b1) {
    asm volatile(
        "mma.sync.aligned.m16n8k16.row.col.f32.bf16.bf16.f32 "
        "{%0,%1,%2,%3}, {%4,%5,%6,%7}, {%8,%9}, {%0,%1,%2,%3};\n"
        : "+f"(c[0]), "+f"(c[1]), "+f"(c[2]), "+f"(c[3])
        : "r"(a0), "r"(a1), "r"(a2), "r"(a3), "r"(b0), "r"(b1));
}

__device__ __forceinline__ void split2(float x, float y, unsigned& h, unsigned& l) {
    __nv_bfloat16 bx = __float2bfloat16_rn(x);
    __nv_bfloat16 by = __float2bfloat16_rn(y);
    __nv_bfloat162 hv; hv.x = bx; hv.y = by;
    h = *(unsigned*)&hv;
    __nv_bfloat162 lv = __floats2bfloat162_rn(x - __bfloat162float(bx),
                                              y - __bfloat162float(by));
    l = *(unsigned*)&lv;
}

__device__ __forceinline__ void cp16(unsigned smem_addr, const void* gptr) {
    asm volatile("cp.async.cg.shared.global [%0], [%1], 16;"
                 :: "r"(smem_addr), "l"(gptr));
}

__device__ __forceinline__ void red_rel(unsigned* p, unsigned v) {
    asm volatile("red.release.gpu.global.add.u32 [%0], %1;" :: "l"(p), "r"(v) : "memory");
}

__device__ __forceinline__ void st_rel(unsigned* p, unsigned v) {
    asm volatile("st.release.gpu.global.u32 [%0], %1;" :: "l"(p), "r"(v) : "memory");
}

// producer slab conversion
__device__ __forceinline__ void cvt_store_slab(__nv_bfloat16* hi, __nv_bfloat16* lo,
                                               int row, int seg, float4 v) {
    int idx = row * 20 + seg * 4;
    __nv_bfloat16 hx = __float2bfloat16_rn(v.x);
    __nv_bfloat16 hy = __float2bfloat16_rn(v.y);
    __nv_bfloat16 hz = __float2bfloat16_rn(v.z);
    __nv_bfloat16 hw = __float2bfloat16_rn(v.w);
    float lx = v.x - __bfloat162float(hx);
    float ly = v.y - __bfloat162float(hy);
    float lz = v.z - __bfloat162float(hz);
    float lw = v.w - __bfloat162float(hw);
    __nv_bfloat162 h01; h01.x = hx; h01.y = hy;
    __nv_bfloat162 h23; h23.x = hz; h23.y = hw;
    *(__nv_bfloat162*)&hi[idx]     = h01;
    *(__nv_bfloat162*)&hi[idx + 2] = h23;
    *(__nv_bfloat162*)&lo[idx]     = __floats2bfloat162_rn(lx, ly);
    *(__nv_bfloat162*)&lo[idx + 2] = __floats2bfloat162_rn(lz, lw);
}

// ---------------------------------------------------------------------------
extern __shared__ float smem_dyn[];

__global__ void __launch_bounds__(NTHR, 1)
lstm_fused_kernel(const float* __restrict__ embs,
                  const float* __restrict__ w_ih,
                  const float* __restrict__ w_hh,
                  const float* __restrict__ b_ih,
                  const float* __restrict__ b_hh,
                  const float* __restrict__ c0,
                  float* __restrict__ out) {
    unsigned* wfH = (unsigned*)smem_dyn + WFH_OFF;
    unsigned* wfL = (unsigned*)smem_dyn + WFL_OFF;
    unsigned* hst = (unsigned*)smem_dyn + HST_OFF;
    float*    hp  = smem_dyn + HP_OFF;
    __nv_bfloat16* gx = (__nv_bfloat16*)((unsigned*)smem_dyn + GX_OFF);

    const int tid = threadIdx.x;
    const int blk = blockIdx.x;

    if (tid < 256) {
        // =============== RECURRENCE GROUP (warps 0-7, tensor core) ==========
        const int c_base = blk * 8;
        const int w    = tid >> 5;
        const int lane = tid & 31;
        const int g    = lane >> 2;
        const int tg   = lane & 3;
        const int s0    = blk & 7;            // chunk-order skew

        // ---- pre-pack W fragments (hi/lo) into smem, mma-ready layout ----
        for (int c = 0; c < 8; c++) {
            int ks = c * 8 + w;
            int k0 = c * 128 + w * 16 + 2 * tg;
#pragma unroll
            for (int mt = 0; mt < 2; mt++) {
                int r0 = mt * 16 + g;
                int r1 = r0 + 8;
                const float* row0 = w_hh + (size_t)((r0 >> 3) * KD + c_base + (r0 & 7)) * KD;
                const float* row1 = w_hh + (size_t)((r1 >> 3) * KD + c_base + (r1 & 7)) * KD;
                unsigned h0, h1, h2, h3, l0, l1, l2, l3;
                split2(row0[k0],     row0[k0 + 1], h0, l0);
                split2(row1[k0],     row1[k0 + 1], h1, l1);
                split2(row0[k0 + 8], row0[k0 + 9], h2, l2);
                split2(row1[k0 + 8], row1[k0 + 9], h3, l3);
                int off = (ks * 2 + mt) * 128 + lane * 4;
                *(uint4*)(wfH + off) = make_uint4(h0, h1, h2, h3);
                *(uint4*)(wfL + off) = make_uint4(l0, l1, l2, l3);
            }
        }

        const int eb = lane;            // batch
        const int ec = c_base + w;      // cell index
        float c_state = c0[ec];
        const int krow = tid >> 1;      // staging: k row 0..127
        const int half = tid & 1;       // staging: b half

        unsigned hst_u32;
        {
            unsigned long long tmp = (unsigned long long)__cvta_generic_to_shared(hst);
            hst_u32 = (unsigned)tmp;
        }
        const unsigned my_dst_off = ((unsigned)(krow * 36 + half * 16)) << 2;

        // per-warp flag dependencies: chunk ci needs blocks ci*16+2w, +1
        // lanes 0..15: skew position lane>>1, block parity lane&1
        const int poll_ci  = (((lane >> 1) + s0) & 7);
        const unsigned* poll_fp = &g_bflag[poll_ci * 16 + 2 * w + (lane & 1)];

        NB_REC();

        for (int t = 0; t < TT; t++) {
            const unsigned* hin = g_hpk[t & 1];
            unsigned*      hout = g_hpk[(t & 1) ^ 1];
            const unsigned t_u = (unsigned)t;

            // ---- ONE warp-wide poll: lanes 0-15 block flags, lane 16 xflag ----
            unsigned rdy;
            {
                const volatile unsigned* xf = &g_xflag[t >> 2];
                while (true) {
                    bool ok;
                    if (lane < 16)       ok = (*(volatile const unsigned*)poll_fp >= t_u);
                    else if (lane == 16) ok = (*xf >= 32u);
                    else                 ok = true;
                    rdy = __ballot_sync(0xffffffffu, ok);
                    if ((rdy & 0x1003Fu) == 0x1003Fu) break;
                    __nanosleep(24);
                }
            }

            // ---- issue first 3 chunks (skewed order), already gated ----
            const unsigned* my_src = hin + krow * 32 + half * 16;
#pragma unroll
            for (int i = 0; i < 3; i++) {
                int ci = (i + s0) & 7;
                unsigned dst = hst_u32 + ((unsigned)((i % 3) * 4608) << 2) + my_dst_off;
                const unsigned* src = my_src + ci * 4096;
                cp16(dst,      src);
                cp16(dst + 16, src + 4);
                cp16(dst + 32, src + 8);
                cp16(dst + 48, src + 12);
                asm volatile("cp.async.commit_group;" ::: "memory");
            }

            // x prefetch (consumed at epilogue — long slack)
            const float* xq = g_xproj + ((size_t)t * BB + eb) * GD + ec;
            float x_i = __ldcg(xq);
            float x_f = __ldcg(xq + KD);
            float x_g = __ldcg(xq + 2 * KD);
            float x_o = __ldcg(xq + 3 * KD);

            float acc[2][4][4];
#pragma unroll
            for (int mt = 0; mt < 2; mt++)
#pragma unroll
                for (int nt = 0; nt < 4; nt++)
#pragma unroll
                    for (int q = 0; q < 4; q++) acc[mt][nt][q] = 0.f;

            const int kk = w * 8 + tg;
#pragma unroll
            for (int i = 0; i < 8; i++) {
                // chunk at iteration i has landed when pending <= min(2, 7-i)
                if (i <= 5)      { CP_WAIT_2(); }
                else if (i == 6) { CP_WAIT_1(); }
                else             { CP_WAIT_0(); }
                __syncwarp();   // warp-private rows: intra-warp visibility only

                int ci = (i + s0) & 7;
                int ks = ci * 8 + w;
                uint4 AH0 = *(const uint4*)(wfH + (ks * 2 + 0) * 128 + lane * 4);
                uint4 AH1 = *(const uint4*)(wfH + (ks * 2 + 1) * 128 + lane * 4);
                uint4 AL0 = *(const uint4*)(wfL + (ks * 2 + 0) * 128 + lane * 4);
                uint4 AL1 = *(const uint4*)(wfL + (ks * 2 + 1) * 128 + lane * 4);
                const unsigned* sb = hst + (i % 3) * 4608;
#pragma unroll
                for (int nt = 0; nt < 4; nt++) {
                    const unsigned* p0 = sb + (2 * kk) * 36 + nt * 8 + g;
                    unsigned u00 = p0[0],   u01 = p0[36];
                    unsigned u10 = p0[288], u11 = p0[324];
                    unsigned bh0 = __byte_perm(u00, u01, 0x5410);
                    unsigned bl0 = __byte_perm(u00, u01, 0x7632);
                    unsigned bh1 = __byte_perm(u10, u11, 0x5410);
                    unsigned bl1 = __byte_perm(u10, u11, 0x7632);
                    mma16816(acc[0][nt], AH0.x, AH0.y, AH0.z, AH0.w, bh0, bh1);
                    mma16816(acc[1][nt], AH1.x, AH1.y, AH1.z, AH1.w, bh0, bh1);
                    mma16816(acc[0][nt], AH0.x, AH0.y, AH0.z, AH0.w, bl0, bl1);
                    mma16816(acc[1][nt], AH1.x, AH1.y, AH1.z, AH1.w, bl0, bl1);
                    mma16816(acc[0][nt], AL0.x, AL0.y, AL0.z, AL0.w, bh0, bh1);
                    mma16816(acc[1][nt], AL1.x, AL1.y, AL1.z, AL1.w, bh0, bh1);
                }
                __syncwarp();
                if (i < 5) {
                    int p = i + 3;                   // skew position of reissue
                    int cn = (p + s0) & 7;
                    unsigned m = 3u << (2 * p);
                    if ((rdy & m) != m) {            // slow path: 2-lane poll
                        if (lane < 2) {
                            const volatile unsigned* fp2 =
                                &g_bflag[cn * 16 + 2 * w + lane];
                            while (*fp2 < t_u) __nanosleep(20);
                        }
                        __syncwarp();
                    }
                    unsigned dst = hst_u32 + ((unsigned)((i % 3) * 4608) << 2) + my_dst_off;
                    const unsigned* src = my_src + cn * 4096;
                    cp16(dst,      src);
                    cp16(dst + 16, src + 4);
                    cp16(dst + 32, src + 8);
                    cp16(dst + 48, src + 12);
                    asm volatile("cp.async.commit_group;" ::: "memory");
                }
            }

            // ---- reduction: warps 4-7 write partials immediately (own region)
            if (w >= 4) {
                float* buf = hp + (w - 4) * 1088;
#pragma unroll
                for (int mt = 0; mt < 2; mt++)
#pragma unroll
                    for (int nt = 0; nt < 4; nt++) {
                        int r0 = mt * 16 + g, col = nt * 8 + 2 * tg;
                        *(float2*)&buf[r0 * 34 + col] =
                            make_float2(acc[mt][nt][0], acc[mt][nt][1]);
                        *(float2*)&buf[(r0 + 8) * 34 + col] =
                            make_float2(acc[mt][nt][2], acc[mt][nt][3]);
                    }
            }
            NB_REC();
            if (w < 4) {
                float* buf = hp + w * 1088;
#pragma unroll
                for (int mt = 0; mt < 2; mt++)
#pragma unroll
                    for (int nt = 0; nt < 4; nt++) {
                        int r0 = mt * 16 + g, col = nt * 8 + 2 * tg;
                        float2 p0 = *(float2*)&buf[r0 * 34 + col];
                        float2 p1 = *(float2*)&buf[(r0 + 8) * 34 + col];
                        p0.x += acc[mt][nt][0]; p0.y += acc[mt][nt][1];
                        p1.x += acc[mt][nt][2]; p1.y += acc[mt][nt][3];
                        *(float2*)&buf[r0 * 34 + col] = p0;
                        *(float2*)&buf[(r0 + 8) * 34 + col] = p1;
                    }
            }
            NB_REC();

            // ---- fused gate epilogue: thread = (cl=w, b=eb) ----
            float gv[4];
#pragma unroll
            for (int gate = 0; gate < 4; gate++) {
                int ro = (gate * 8 + w) * 34 + eb;
                gv[gate] = hp[ro] + hp[1088 + ro] + hp[2176 + ro] + hp[3264 + ro];
            }
            float gi = x_i + gv[0], gf = x_f + gv[1];
            float gg = x_g + gv[2], go = x_o + gv[3];
            float ig = 1.f / (1.f + __expf(-gi));
            float fg = 1.f / (1.f + __expf(-gf));
            float gt = tanhf(gg);
            float og = 1.f / (1.f + __expf(-go));
            c_state  = fg * c_state + ig * gt;
            float hn = og * tanhf(c_state);

            // h store FIRST (on the inter-block critical path)
            {
                __nv_bfloat16 hb = __float2bfloat16_rn(hn);
                __nv_bfloat16 lb = __float2bfloat16_rn(hn - __bfloat162float(hb));
                unsigned up = (unsigned)*(unsigned short*)&hb |
                              ((unsigned)*(unsigned short*)&lb << 16);
                asm volatile("st.global.cg.u32 [%0], %1;"
                             :: "l"(&hout[ec * 32 + eb]), "r"(up) : "memory");
            }
            NB_REC();
            if (tid == 0) st_rel(&g_bflag[blk], t_u + 1u);   // single-writer release

            // out store off the critical path
            out[((size_t)t * BB + eb) * KD + ec] = hn;
        }
    } else {
        // ====== XPROJ PRODUCER (warps 8-15): bf16-split HMMA, 1-stage =======
        const int tid2 = tid - 256;
        const int x_b  = blk & 31;
        const int y_b  = blk >> 5;
        const int bn   = x_b * 128;

        const int wid2 = tid2 >> 5;
        const int lane = tid2 & 31;
        const int wm   = wid2 >> 2;
        const int wn   = wid2 & 3;
        const int g    = lane >> 2;
        const int tg   = lane & 3;

        const int srow = tid2 >> 2;
        const int seg  = tid2 & 3;

        float bias0[4], bias1[4];
#pragma unroll
        for (int nf = 0; nf < 4; nf++) {
            int cc = bn + wn * 32 + nf * 8 + 2 * tg;
            bias0[nf] = __ldg(&b_ih[cc])     + __ldg(&b_hh[cc]);
            bias1[nf] = __ldg(&b_ih[cc + 1]) + __ldg(&b_hh[cc + 1]);
        }

        __nv_bfloat16* stg = gx;   // single stage (Ahi, Alo, Whi, Wlo)

        const float4* Wg0 = (const float4*)(w_ih + (size_t)(bn + srow) * KD + seg * 4);
        const float4* Wg1 = (const float4*)(w_ih + (size_t)(bn + srow + 64) * KD + seg * 4);

        for (int it = 0; it < 32; it++) {
            const int y  = y_b + 4 * it;
            const int bm = y * 128;
            const float4* Ag0 = (const float4*)(embs + (size_t)(bm + srow) * KD + seg * 4);
            const float4* Ag1 = (const float4*)(embs + (size_t)(bm + srow + 64) * KD + seg * 4);

            float acc[4][4][4];
#pragma unroll
            for (int i = 0; i < 4; i++)
#pragma unroll
                for (int j = 0; j < 4; j++)
#pragma unroll
                    for (int q = 0; q < 4; q++) acc[i][j][q] = 0.f;

            float4 a0 = __ldg(Ag0), a1 = __ldg(Ag1);
            float4 w0 = __ldg(Wg0), w1 = __ldg(Wg1);

            for (int s = 0; s < 64; s++) {
                NB_GEM();   // all warps done computing previous slab
                cvt_store_slab(stg,        stg + 2560, srow,      seg, a0);
                cvt_store_slab(stg,        stg + 2560, srow + 64, seg, a1);
                cvt_store_slab(stg + 5120, stg + 7680, srow,      seg, w0);
                cvt_store_slab(stg + 5120, stg + 7680, srow + 64, seg, w1);
                NB_GEM();   // staging complete
                if (s < 63) {
                    a0 = __ldg(Ag0 + (s + 1) * 4);
                    a1 = __ldg(Ag1 + (s + 1) * 4);
                    w0 = __ldg(Wg0 + (s + 1) * 4);
                    w1 = __ldg(Wg1 + (s + 1) * 4);
                }

                const unsigned* Ahi = (const unsigned*)(stg);
                const unsigned* Alo = (const unsigned*)(stg + 2560);
                const unsigned* Whi = (const unsigned*)(stg + 5120);
                const unsigned* Wlo = (const unsigned*)(stg + 7680);

                unsigned bh[4][2], bl[4][2];
#pragma unroll
                for (int nf = 0; nf < 4; nf++) {
                    int nrow = wn * 32 + nf * 8 + g;
                    bh[nf][0] = Whi[nrow * 10 + tg];
                    bh[nf][1] = Whi[nrow * 10 + tg + 4];
                    bl[nf][0] = Wlo[nrow * 10 + tg];
                    bl[nf][1] = Wlo[nrow * 10 + tg + 4];
                }
#pragma unroll
                for (int mf = 0; mf < 4; mf++) {
                    int ar = (wm * 64 + mf * 16 + g) * 10;
                    unsigned a0f = Ahi[ar + tg];
                    unsigned a1f = Ahi[ar + 80 + tg];
                    unsigned a2f = Ahi[ar + tg + 4];
                    unsigned a3f = Ahi[ar + 80 + tg + 4];
#pragma unroll
                    for (int nf = 0; nf < 4; nf++) {
                        mma16816(acc[mf][nf], a0f, a1f, a2f, a3f, bh[nf][0], bh[nf][1]);
                        mma16816(acc[mf][nf], a0f, a1f, a2f, a3f, bl[nf][0], bl[nf][1]);
                    }
                }
#pragma unroll
                for (int mf = 0; mf < 4; mf++) {
                    int ar = (wm * 64 + mf * 16 + g) * 10;
                    unsigned a0f = Alo[ar + tg];
                    unsigned a1f = Alo[ar + 80 + tg];
                    unsigned a2f = Alo[ar + tg + 4];
                    unsigned a3f = Alo[ar + 80 + tg + 4];
#pragma unroll
                    for (int nf = 0; nf < 4; nf++) {
                        mma16816(acc[mf][nf], a0f, a1f, a2f, a3f, bh[nf][0], bh[nf][1]);
                    }
                }
            }

#pragma unroll
            for (int mf = 0; mf < 4; mf++) {
                int r0 = bm + wm * 64 + mf * 16 + g;
#pragma unroll
                for (int nf = 0; nf < 4; nf++) {
                    int cc = bn + wn * 32 + nf * 8 + 2 * tg;
                    float2 v0, v1;
                    v0.x = acc[mf][nf][0] + bias0[nf];
                    v0.y = acc[mf][nf][1] + bias1[nf];
                    v1.x = acc[mf][nf][2] + bias0[nf];
                    v1.y = acc[mf][nf][3] + bias1[nf];
                    __stcg((float2*)&g_xproj[(size_t)r0 * GD + cc], v0);
                    __stcg((float2*)&g_xproj[(size_t)(r0 + 8) * GD + cc], v1);
                }
            }

            NB_GEM();
            if (tid2 == 0) red_rel(&g_xflag[y], 1u);
        }
    }
}

// ---------------------------------------------------------------------------
extern "C" void kernel_launch(void* const* d_in, const int* in_sizes, int n_in,
                              void* d_out, int out_size) {
    const float* embs = (const float*)d_in[0];
    const float* w_ih = (const float*)d_in[1];
    const float* w_hh = (const float*)d_in[2];
    const float* b_ih = (const float*)d_in[3];
    const float* b_hh = (const float*)d_in[4];
    const float* h0   = (const float*)d_in[5];
    const float* c0   = (const float*)d_in[6];
    float* out = (float*)d_out;

    init_state_kernel<<<128, 256>>>(h0);

    static int smem_set = 0;
    const int smem_bytes = SMEM_WORDS * (int)sizeof(float);  // 224256 B
    if (!smem_set) {
        cudaFuncSetAttribute(lstm_fused_kernel,
                             cudaFuncAttributeMaxDynamicSharedMemorySize,
                             smem_bytes);
        smem_set = 1;
    }
    lstm_fused_kernel<<<NBLK, NTHR, smem_bytes>>>(embs, w_ih, w_hh, b_ih, b_hh,
                                                  c0, out);
}

// round 16
// speedup vs baseline: 1.5785x; 1.5785x over previous
#include <cuda_runtime.h>
#include <cuda_bf16.h>
#include <math.h>

#define TT 512
#define BB 32
#define KD 1024
#define GD 4096
#define NBLK 128
#define NTHR 512

// Scratch
__device__ float g_xproj[(size_t)TT * BB * GD];
__device__ __align__(16) unsigned g_hpk[2][KD * BB];   // [k][b], hi|lo<<16 packed bf16
__device__ __align__(32) unsigned g_ckcnt[8];   // 8 counters in ONE 32B line
__device__ unsigned g_xflag[128];   // y-chunk -> # n-tiles finished (target 32)

#define NB_REC() asm volatile("bar.sync 1, 256;" ::: "memory")
#define NB_GEM() asm volatile("bar.sync 2, 256;" ::: "memory")

// smem word offsets (4B words)
#define WFH_OFF 0          // W frags hi: 16384 words (64 KB)
#define WFL_OFF 16384      // W frags lo: 16384 words (64 KB)
#define HST_OFF 32768      // h chunk bufs: 3 x 4608 = 13824 words (55.3 KB)
#define HP_OFF  46592      // partials: 4352 words (17.4 KB) — own region
#define GX_OFF  50944      // producer single stage: 5120 words (20 KB)
#define SMEM_WORDS 56064   // 224256 B

#define CP_WAIT_2() asm volatile("cp.async.wait_group 2;" ::: "memory")
#define CP_WAIT_1() asm volatile("cp.async.wait_group 1;" ::: "memory")
#define CP_WAIT_0() asm volatile("cp.async.wait_group 0;" ::: "memory")

// ---------------------------------------------------------------------------
__global__ void init_state_kernel(const float* __restrict__ h0) {
    int i = blockIdx.x * blockDim.x + threadIdx.x;   // 0..32767 = k*32 + b
    int k = i >> 5;
    float v = h0[k];
    __nv_bfloat16 hb = __float2bfloat16_rn(v);
    __nv_bfloat16 lb = __float2bfloat16_rn(v - __bfloat162float(hb));
    g_hpk[0][i] = (unsigned)*(unsigned short*)&hb |
                  ((unsigned)*(unsigned short*)&lb << 16);
    if (i < 8) g_ckcnt[i] = 0u;
    if (i < 128) g_xflag[i] = 0u;
}

// ---------------------------------------------------------------------------
__device__ __forceinline__ void mma16816(float* c,
                                         unsigned a0, unsigned a1, unsigned a2, unsigned a3,
                                         unsigned b0, unsigned b1) {
    asm volatile(
        "mma.sync.aligned.m16n8k16.row.col.f32.bf16.bf16.f32 "
        "{%0,%1,%2,%3}, {%4,%5,%6,%7}, {%8,%9}, {%0,%1,%2,%3};\n"
        : "+f"(c[0]), "+f"(c[1]), "+f"(c[2]), "+f"(c[3])
        : "r"(a0), "r"(a1), "r"(a2), "r"(a3), "r"(b0), "r"(b1));
}

__device__ __forceinline__ void split2(float x, float y, unsigned& h, unsigned& l) {
    __nv_bfloat16 bx = __float2bfloat16_rn(x);
    __nv_bfloat16 by = __float2bfloat16_rn(y);
    __nv_bfloat162 hv; hv.x = bx; hv.y = by;
    h = *(unsigned*)&hv;
    __nv_bfloat162 lv = __floats2bfloat162_rn(x - __bfloat162float(bx),
                                              y - __bfloat162float(by));
    l = *(unsigned*)&lv;
}

__device__ __forceinline__ void cp16(unsigned smem_addr, const void* gptr) {
    asm volatile("cp.async.cg.shared.global [%0], [%1], 16;"
                 :: "r"(smem_addr), "l"(gptr));
}

__device__ __forceinline__ void red_rel(unsigned* p, unsigned v) {
    asm volatile("red.release.gpu.global.add.u32 [%0], %1;" :: "l"(p), "r"(v) : "memory");
}

// lane-0-only re-poll of one counter (slow path)
__device__ __forceinline__ void warp_wait_cnt(const unsigned* p, unsigned tgt, int lane) {
    if (lane == 0) {
        while (*(volatile const unsigned*)p < tgt) __nanosleep(20);
    }
    __syncwarp();
}

// producer slab conversion
__device__ __forceinline__ void cvt_store_slab(__nv_bfloat16* hi, __nv_bfloat16* lo,
                                               int row, int seg, float4 v) {
    int idx = row * 20 + seg * 4;
    __nv_bfloat16 hx = __float2bfloat16_rn(v.x);
    __nv_bfloat16 hy = __float2bfloat16_rn(v.y);
    __nv_bfloat16 hz = __float2bfloat16_rn(v.z);
    __nv_bfloat16 hw = __float2bfloat16_rn(v.w);
    float lx = v.x - __bfloat162float(hx);
    float ly = v.y - __bfloat162float(hy);
    float lz = v.z - __bfloat162float(hz);
    float lw = v.w - __bfloat162float(hw);
    __nv_bfloat162 h01; h01.x = hx; h01.y = hy;
    __nv_bfloat162 h23; h23.x = hz; h23.y = hw;
    *(__nv_bfloat162*)&hi[idx]     = h01;
    *(__nv_bfloat162*)&hi[idx + 2] = h23;
    *(__nv_bfloat162*)&lo[idx]     = __floats2bfloat162_rn(lx, ly);
    *(__nv_bfloat162*)&lo[idx + 2] = __floats2bfloat162_rn(lz, lw);
}

// ---------------------------------------------------------------------------
extern __shared__ float smem_dyn[];

__global__ void __launch_bounds__(NTHR, 1)
lstm_fused_kernel(const float* __restrict__ embs,
                  const float* __restrict__ w_ih,
                  const float* __restrict__ w_hh,
                  const float* __restrict__ b_ih,
                  const float* __restrict__ b_hh,
                  const float* __restrict__ c0,
                  float* __restrict__ out) {
    unsigned* wfH = (unsigned*)smem_dyn + WFH_OFF;
    unsigned* wfL = (unsigned*)smem_dyn + WFL_OFF;
    unsigned* hst = (unsigned*)smem_dyn + HST_OFF;
    float*    hp  = smem_dyn + HP_OFF;
    __nv_bfloat16* gx = (__nv_bfloat16*)((unsigned*)smem_dyn + GX_OFF);

    const int tid = threadIdx.x;
    const int blk = blockIdx.x;

    if (tid < 256) {
        // =============== RECURRENCE GROUP (warps 0-7, tensor core) ==========
        const int c_base = blk * 8;
        const int w    = tid >> 5;
        const int lane = tid & 31;
        const int g    = lane >> 2;
        const int tg   = lane & 3;
        const int mygrp = blk >> 4;           // chunk this block produces
        const int s0    = blk & 7;            // chunk-order skew

        // ---- pre-pack W fragments (hi/lo) into smem, mma-ready layout ----
        for (int c = 0; c < 8; c++) {
            int ks = c * 8 + w;
            int k0 = c * 128 + w * 16 + 2 * tg;
#pragma unroll
            for (int mt = 0; mt < 2; mt++) {
                int r0 = mt * 16 + g;
                int r1 = r0 + 8;
                const float* row0 = w_hh + (size_t)((r0 >> 3) * KD + c_base + (r0 & 7)) * KD;
                const float* row1 = w_hh + (size_t)((r1 >> 3) * KD + c_base + (r1 & 7)) * KD;
                unsigned h0, h1, h2, h3, l0, l1, l2, l3;
                split2(row0[k0],     row0[k0 + 1], h0, l0);
                split2(row1[k0],     row1[k0 + 1], h1, l1);
                split2(row0[k0 + 8], row0[k0 + 9], h2, l2);
                split2(row1[k0 + 8], row1[k0 + 9], h3, l3);
                int off = (ks * 2 + mt) * 128 + lane * 4;
                *(uint4*)(wfH + off) = make_uint4(h0, h1, h2, h3);
                *(uint4*)(wfL + off) = make_uint4(l0, l1, l2, l3);
            }
        }

        const int eb = lane;            // batch
        const int ec = c_base + w;      // cell index
        float c_state = c0[ec];
        const int krow = tid >> 1;      // staging: k row 0..127
        const int half = tid & 1;       // staging: b half

        unsigned hst_u32;
        {
            unsigned long long tmp = (unsigned long long)__cvta_generic_to_shared(hst);
            hst_u32 = (unsigned)tmp;
        }
        const unsigned my_dst_off = ((unsigned)(krow * 36 + half * 16)) << 2;

        // exit poll as soon as FIRST chunk + xflag ready; rest via snapshot
        const unsigned need0 = (1u << s0) | (1u << 8);

        NB_REC();

        for (int t = 0; t < TT; t++) {
            const unsigned* hin = g_hpk[t & 1];
            unsigned*      hout = g_hpk[(t & 1) ^ 1];
            const unsigned tgt = 16u * (unsigned)t;

            // ---- ONE warp-wide poll: lanes 0-7 counters, lane 8 xflag ----
            unsigned rdy;
            {
                const volatile unsigned* cp_ = &g_ckcnt[lane & 7];
                const volatile unsigned* xf  = &g_xflag[t >> 2];
                while (true) {
                    bool ok;
                    if (lane < 8)       ok = (*cp_ >= tgt);
                    else if (lane == 8) ok = (*xf >= 32u);
                    else                ok = true;
                    rdy = __ballot_sync(0xffffffffu, ok);
                    if ((rdy & need0) == need0) break;
                    __nanosleep(24);
                }
            }

            // ---- issue first 3 chunks (skewed order) ----
            const unsigned* my_src = hin + krow * 32 + half * 16;
#pragma unroll
            for (int i = 0; i < 3; i++) {
                int ci = (i + s0) & 7;
                if (i > 0 && !((rdy >> ci) & 1u))
                    warp_wait_cnt(&g_ckcnt[ci], tgt, lane);   // slow path only
                unsigned dst = hst_u32 + ((unsigned)((i % 3) * 4608) << 2) + my_dst_off;
                const unsigned* src = my_src + ci * 4096;
                cp16(dst,      src);
                cp16(dst + 16, src + 4);
                cp16(dst + 32, src + 8);
                cp16(dst + 48, src + 12);
                asm volatile("cp.async.commit_group;" ::: "memory");
            }

            // x prefetch (consumed at epilogue — long slack)
            const float* xq = g_xproj + ((size_t)t * BB + eb) * GD + ec;
            float x_i = __ldcg(xq);
            float x_f = __ldcg(xq + KD);
            float x_g = __ldcg(xq + 2 * KD);
            float x_o = __ldcg(xq + 3 * KD);

            float acc[2][4][4];
#pragma unroll
            for (int mt = 0; mt < 2; mt++)
#pragma unroll
                for (int nt = 0; nt < 4; nt++)
#pragma unroll
                    for (int q = 0; q < 4; q++) acc[mt][nt][q] = 0.f;

            const int kk = w * 8 + tg;
#pragma unroll
            for (int i = 0; i < 8; i++) {
                // chunk at iteration i has landed when pending <= min(2, 7-i)
                if (i <= 5)      { CP_WAIT_2(); }
                else if (i == 6) { CP_WAIT_1(); }
                else             { CP_WAIT_0(); }
                __syncwarp();   // warp-private rows: intra-warp visibility only

                int ci = (i + s0) & 7;
                int ks = ci * 8 + w;
                uint4 AH0 = *(const uint4*)(wfH + (ks * 2 + 0) * 128 + lane * 4);
                uint4 AH1 = *(const uint4*)(wfH + (ks * 2 + 1) * 128 + lane * 4);
                uint4 AL0 = *(const uint4*)(wfL + (ks * 2 + 0) * 128 + lane * 4);
                uint4 AL1 = *(const uint4*)(wfL + (ks * 2 + 1) * 128 + lane * 4);
                const unsigned* sb = hst + (i % 3) * 4608;
#pragma unroll
                for (int nt = 0; nt < 4; nt++) {
                    const unsigned* p0 = sb + (2 * kk) * 36 + nt * 8 + g;
                    unsigned u00 = p0[0],   u01 = p0[36];
                    unsigned u10 = p0[288], u11 = p0[324];
                    unsigned bh0 = __byte_perm(u00, u01, 0x5410);
                    unsigned bl0 = __byte_perm(u00, u01, 0x7632);
                    unsigned bh1 = __byte_perm(u10, u11, 0x5410);
                    unsigned bl1 = __byte_perm(u10, u11, 0x7632);
                    mma16816(acc[0][nt], AH0.x, AH0.y, AH0.z, AH0.w, bh0, bh1);
                    mma16816(acc[1][nt], AH1.x, AH1.y, AH1.z, AH1.w, bh0, bh1);
                    mma16816(acc[0][nt], AH0.x, AH0.y, AH0.z, AH0.w, bl0, bl1);
                    mma16816(acc[1][nt], AH1.x, AH1.y, AH1.z, AH1.w, bl0, bl1);
                    mma16816(acc[0][nt], AL0.x, AL0.y, AL0.z, AL0.w, bh0, bh1);
                    mma16816(acc[1][nt], AL1.x, AL1.y, AL1.z, AL1.w, bh0, bh1);
                }
                __syncwarp();
                if (i < 5) {
                    int cn = (i + 3 + s0) & 7;
                    if (!((rdy >> cn) & 1u))
                        warp_wait_cnt(&g_ckcnt[cn], tgt, lane);   // slow path only
                    unsigned dst = hst_u32 + ((unsigned)((i % 3) * 4608) << 2) + my_dst_off;
                    const unsigned* src = my_src + cn * 4096;
                    cp16(dst,      src);
                    cp16(dst + 16, src + 4);
                    cp16(dst + 32, src + 8);
                    cp16(dst + 48, src + 12);
                    asm volatile("cp.async.commit_group;" ::: "memory");
                }
            }

            // ---- reduction: warps 4-7 write partials immediately (own region)
            if (w >= 4) {
                float* buf = hp + (w - 4) * 1088;
#pragma unroll
                for (int mt = 0; mt < 2; mt++)
#pragma unroll
                    for (int nt = 0; nt < 4; nt++) {
                        int r0 = mt * 16 + g, col = nt * 8 + 2 * tg;
                        *(float2*)&buf[r0 * 34 + col] =
                            make_float2(acc[mt][nt][0], acc[mt][nt][1]);
                        *(float2*)&buf[(r0 + 8) * 34 + col] =
                            make_float2(acc[mt][nt][2], acc[mt][nt][3]);
                    }
            }
            NB_REC();
            if (w < 4) {
                float* buf = hp + w * 1088;
#pragma unroll
                for (int mt = 0; mt < 2; mt++)
#pragma unroll
                    for (int nt = 0; nt < 4; nt++) {
                        int r0 = mt * 16 + g, col = nt * 8 + 2 * tg;
                        float2 p0 = *(float2*)&buf[r0 * 34 + col];
                        float2 p1 = *(float2*)&buf[(r0 + 8) * 34 + col];
                        p0.x += acc[mt][nt][0]; p0.y += acc[mt][nt][1];
                        p1.x += acc[mt][nt][2]; p1.y += acc[mt][nt][3];
                        *(float2*)&buf[r0 * 34 + col] = p0;
                        *(float2*)&buf[(r0 + 8) * 34 + col] = p1;
                    }
            }
            NB_REC();

            // ---- fused gate epilogue: thread = (cl=w, b=eb) ----
            float gv[4];
#pragma unroll
            for (int gate = 0; gate < 4; gate++) {
                int ro = (gate * 8 + w) * 34 + eb;
                gv[gate] = hp[ro] + hp[1088 + ro] + hp[2176 + ro] + hp[3264 + ro];
            }
            float gi = x_i + gv[0], gf = x_f + gv[1];
            float gg = x_g + gv[2], go = x_o + gv[3];
            float ig = 1.f / (1.f + __expf(-gi));
            float fg = 1.f / (1.f + __expf(-gf));
            float gt = tanhf(gg);
            float og = 1.f / (1.f + __expf(-go));
            c_state  = fg * c_state + ig * gt;
            float hn = og * tanhf(c_state);

            // h store FIRST (on the inter-block critical path)
            {
                __nv_bfloat16 hb = __float2bfloat16_rn(hn);
                __nv_bfloat16 lb = __float2bfloat16_rn(hn - __bfloat162float(hb));
                unsigned up = (unsigned)*(unsigned short*)&hb |
                              ((unsigned)*(unsigned short*)&lb << 16);
                asm volatile("st.global.cg.u32 [%0], %1;"
                             :: "l"(&hout[ec * 32 + eb]), "r"(up) : "memory");
            }
            NB_REC();
            if (tid == 0) red_rel(&g_ckcnt[mygrp], 1u);

            // out store off the critical path
            out[((size_t)t * BB + eb) * KD + ec] = hn;
        }
    } else {
        // ====== XPROJ PRODUCER (warps 8-15): bf16-split HMMA, 1-stage =======
        const int tid2 = tid - 256;
        const int x_b  = blk & 31;
        const int y_b  = blk >> 5;
        const int bn   = x_b * 128;

        const int wid2 = tid2 >> 5;
        const int lane = tid2 & 31;
        const int wm   = wid2 >> 2;
        const int wn   = wid2 & 3;
        const int g    = lane >> 2;
        const int tg   = lane & 3;

        const int srow = tid2 >> 2;
        const int seg  = tid2 & 3;

        float bias0[4], bias1[4];
#pragma unroll
        for (int nf = 0; nf < 4; nf++) {
            int cc = bn + wn * 32 + nf * 8 + 2 * tg;
            bias0[nf] = __ldg(&b_ih[cc])     + __ldg(&b_hh[cc]);
            bias1[nf] = __ldg(&b_ih[cc + 1]) + __ldg(&b_hh[cc + 1]);
        }

        __nv_bfloat16* stg = gx;   // single stage (Ahi, Alo, Whi, Wlo)

        const float4* Wg0 = (const float4*)(w_ih + (size_t)(bn + srow) * KD + seg * 4);
        const float4* Wg1 = (const float4*)(w_ih + (size_t)(bn + srow + 64) * KD + seg * 4);

        for (int it = 0; it < 32; it++) {
            const int y  = y_b + 4 * it;
            const int bm = y * 128;
            const float4* Ag0 = (const float4*)(embs + (size_t)(bm + srow) * KD + seg * 4);
            const float4* Ag1 = (const float4*)(embs + (size_t)(bm + srow + 64) * KD + seg * 4);

            float acc[4][4][4];
#pragma unroll
            for (int i = 0; i < 4; i++)
#pragma unroll
                for (int j = 0; j < 4; j++)
#pragma unroll
                    for (int q = 0; q < 4; q++) acc[i][j][q] = 0.f;

            float4 a0 = __ldg(Ag0), a1 = __ldg(Ag1);
            float4 w0 = __ldg(Wg0), w1 = __ldg(Wg1);

            for (int s = 0; s < 64; s++) {
                NB_GEM();   // all warps done computing previous slab
                cvt_store_slab(stg,        stg + 2560, srow,      seg, a0);
                cvt_store_slab(stg,        stg + 2560, srow + 64, seg, a1);
                cvt_store_slab(stg + 5120, stg + 7680, srow,      seg, w0);
                cvt_store_slab(stg + 5120, stg + 7680, srow + 64, seg, w1);
                NB_GEM();   // staging complete
                if (s < 63) {
                    a0 = __ldg(Ag0 + (s + 1) * 4);
                    a1 = __ldg(Ag1 + (s + 1) * 4);
                    w0 = __ldg(Wg0 + (s + 1) * 4);
                    w1 = __ldg(Wg1 + (s + 1) * 4);
                }

                const unsigned* Ahi = (const unsigned*)(stg);
                const unsigned* Alo = (const unsigned*)(stg + 2560);
                const unsigned* Whi = (const unsigned*)(stg + 5120);
                const unsigned* Wlo = (const unsigned*)(stg + 7680);

                unsigned bh[4][2], bl[4][2];
#pragma unroll
                for (int nf = 0; nf < 4; nf++) {
                    int nrow = wn * 32 + nf * 8 + g;
                    bh[nf][0] = Whi[nrow * 10 + tg];
                    bh[nf][1] = Whi[nrow * 10 + tg + 4];
                    bl[nf][0] = Wlo[nrow * 10 + tg];
                    bl[nf][1] = Wlo[nrow * 10 + tg + 4];
                }
#pragma unroll
                for (int mf = 0; mf < 4; mf++) {
                    int ar = (wm * 64 + mf * 16 + g) * 10;
                    unsigned a0f = Ahi[ar + tg];
                    unsigned a1f = Ahi[ar + 80 + tg];
                    unsigned a2f = Ahi[ar + tg + 4];
                    unsigned a3f = Ahi[ar + 80 + tg + 4];
#pragma unroll
                    for (int nf = 0; nf < 4; nf++) {
                        mma16816(acc[mf][nf], a0f, a1f, a2f, a3f, bh[nf][0], bh[nf][1]);
                        mma16816(acc[mf][nf], a0f, a1f, a2f, a3f, bl[nf][0], bl[nf][1]);
                    }
                }
#pragma unroll
                for (int mf = 0; mf < 4; mf++) {
                    int ar = (wm * 64 + mf * 16 + g) * 10;
                    unsigned a0f = Alo[ar + tg];
                    unsigned a1f = Alo[ar + 80 + tg];
                    unsigned a2f = Alo[ar + tg + 4];
                    unsigned a3f = Alo[ar + 80 + tg + 4];
#pragma unroll
                    for (int nf = 0; nf < 4; nf++) {
                        mma16816(acc[mf][nf], a0f, a1f, a2f, a3f, bh[nf][0], bh[nf][1]);
                    }
                }
            }

#pragma unroll
            for (int mf = 0; mf < 4; mf++) {
                int r0 = bm + wm * 64 + mf * 16 + g;
#pragma unroll
                for (int nf = 0; nf < 4; nf++) {
                    int cc = bn + wn * 32 + nf * 8 + 2 * tg;
                    float2 v0, v1;
                    v0.x = acc[mf][nf][0] + bias0[nf];
                    v0.y = acc[mf][nf][1] + bias1[nf];
                    v1.x = acc[mf][nf][2] + bias0[nf];
                    v1.y = acc[mf][nf][3] + bias1[nf];
                    __stcg((float2*)&g_xproj[(size_t)r0 * GD + cc], v0);
                    __stcg((float2*)&g_xproj[(size_t)(r0 + 8) * GD + cc], v1);
                }
            }

            NB_GEM();
            if (tid2 == 0) red_rel(&g_xflag[y], 1u);
        }
    }
}

// ---------------------------------------------------------------------------
extern "C" void kernel_launch(void* const* d_in, const int* in_sizes, int n_in,
                              void* d_out, int out_size) {
    const float* embs = (const float*)d_in[0];
    const float* w_ih = (const float*)d_in[1];
    const float* w_hh = (const float*)d_in[2];
    const float* b_ih = (const float*)d_in[3];
    const float* b_hh = (const float*)d_in[4];
    const float* h0   = (const float*)d_in[5];
    const float* c0   = (const float*)d_in[6];
    float* out = (float*)d_out;

    init_state_kernel<<<128, 256>>>(h0);

    static int smem_set = 0;
    const int smem_bytes = SMEM_WORDS * (int)sizeof(float);  // 224256 B
    if (!smem_set) {
        cudaFuncSetAttribute(lstm_fused_kernel,
                             cudaFuncAttributeMaxDynamicSharedMemorySize,
                             smem_bytes);
        smem_set = 1;
    }
    lstm_fused_kernel<<<NBLK, NTHR, smem_bytes>>>(embs, w_ih, w_hh, b_ih, b_hh,
                                                  c0, out);
}